// round 15
// baseline (speedup 1.0000x reference)
#include <cuda_runtime.h>
#include <cstdint>
#include <cuda_fp16.h>
#include <mma.h>

using namespace nvcuda;

namespace {
constexpr int B  = 4;
constexpr int H  = 16;
constexpr int S  = 1024;
constexpr int D  = 1024;
constexpr int HB = H * B;
constexpr float INV_SCALE = 1.0f / 32.0f;        // 1/sqrt(D)
constexpr size_t OUT_ELEMS = (size_t)B * S * D;

// half GEMM tiling (3-stage pipeline) — unchanged from the 309us version
constexpr int G_LD = 72;
constexpr int G_BUF = 128 * G_LD;
constexpr size_t GEMM_SMEM = (size_t)6 * G_BUF * 2;   // 110592

// attention tiling
constexpr int QT = 64;
constexpr int CK = 128;
constexpr int Q_LD = 72;     // halfs
constexpr int K_LD = 72;     // halfs
constexpr int P_LD = 136;    // halfs
constexpr int R_LD = 68;     // floats
constexpr int SC_LD = 132;   // floats (score staging)

constexpr int STAT_OFF = QT * Q_LD * 2;              // 9216  (after Qs)
constexpr int STAT2_OFF = STAT_OFF + 64 * 2 * 4;     // 9728  ([8][64] chunk maxima)
constexpr int KV_OFF = STAT2_OFF + 8 * 64 * 4;       // 11776
constexpr int KBUF_BYTES = CK * K_LD * 2;            // 18432
constexpr int SC_OFF = KV_OFF + 3 * KBUF_BYTES;      // 67072
constexpr size_t ATTN_SMEM = (size_t)SC_OFF + QT * SC_LD * 4;   // 100864
// phase-3 aliases (start at KV_OFF, clear of the stats tables)
constexpr int AS3_OFF = KV_OFF;                      // [64][P_LD] half  = 17408
constexpr int VS3_OFF = AS3_OFF + QT * P_LD * 2;     // [128][K_LD] half = 18432
constexpr int RED_OFF = VS3_OFF + CK * K_LD * 2;     // [64][R_LD] f32
constexpr int RED2_OFF = RED_OFF + QT * R_LD * 4;
}

// Scratch (__device__ globals; allocation-free rule)
__device__ __half g_hxq[(size_t)B * S * D];
__device__ __half g_hxk[(size_t)B * S * D];
__device__ __half g_hxv[(size_t)B * S * D];
__device__ __half g_hwq[(size_t)D * D];          // transposed [n][d]
__device__ __half g_hwk[(size_t)D * D];
__device__ __half g_hwv[(size_t)D * D];
__device__ __half g_hwp[(size_t)D * D];          // [n][k]
__device__ __half g_q[(size_t)B * S * D];        // proj outputs, [m][h*64+k]
__device__ __half g_k[(size_t)B * S * D];
__device__ __half g_v[(size_t)B * S * D];
__device__ __half g_ctx[(size_t)B * S * D];      // [m][h*64+v]

using HFragA  = wmma::fragment<wmma::matrix_a, 16, 16, 16, __half, wmma::row_major>;
using HFragBr = wmma::fragment<wmma::matrix_b, 16, 16, 16, __half, wmma::row_major>;
using HFragBc = wmma::fragment<wmma::matrix_b, 16, 16, 16, __half, wmma::col_major>;
using HFragC  = wmma::fragment<wmma::accumulator, 16, 16, 16, float>;

__device__ __forceinline__ void cp16h(__half* dst, const __half* src) {
    unsigned int s = (unsigned int)__cvta_generic_to_shared(dst);
    asm volatile("cp.async.cg.shared.global [%0], [%1], 16;" :: "r"(s), "l"(src));
}
__device__ __forceinline__ void cp_commit() { asm volatile("cp.async.commit_group;"); }
template <int N> __device__ __forceinline__ void cp_wait() {
    asm volatile("cp.async.wait_group %0;" :: "n"(N));
}

// ---------------------------------------------------------------------------
// Kernel 0a: fp32 -> fp16 for the three X tensors (y-indexed).
// ---------------------------------------------------------------------------
__global__ void __launch_bounds__(256)
f2h3_kernel(const float4* __restrict__ s0, const float4* __restrict__ s1,
            const float4* __restrict__ s2, int n4)
{
    const float4* src = (blockIdx.y == 0) ? s0 : (blockIdx.y == 1) ? s1 : s2;
    __half2* dst = (blockIdx.y == 0) ? (__half2*)g_hxq
                 : (blockIdx.y == 1) ? (__half2*)g_hxk : (__half2*)g_hxv;
    int i = blockIdx.x * 256 + threadIdx.x;
    if (i < n4) {
        float4 v = src[i];
        dst[2 * i + 0] = __floats2half2_rn(v.x, v.y);
        dst[2 * i + 1] = __floats2half2_rn(v.z, v.w);
    }
}

__global__ void __launch_bounds__(256)
f2h_kernel(const float4* __restrict__ src, __half2* __restrict__ dst, int n4)
{
    int i = blockIdx.x * 256 + threadIdx.x;
    if (i < n4) {
        float4 v = src[i];
        dst[2 * i + 0] = __floats2half2_rn(v.x, v.y);
        dst[2 * i + 1] = __floats2half2_rn(v.z, v.w);
    }
}

// ---------------------------------------------------------------------------
// Kernel 0b: W[h][d][kk] -> Wt[(h*64+kk)][d] in fp16. grid (16, 16, 3).
// ---------------------------------------------------------------------------
__global__ void __launch_bounds__(256)
wtrans_kernel(const float* __restrict__ wq, const float* __restrict__ wk,
              const float* __restrict__ wv)
{
    const int which = blockIdx.z;
    const float* W = (which == 0) ? wq : (which == 1) ? wk : wv;
    __half* OUT    = (which == 0) ? g_hwq : (which == 1) ? g_hwk : g_hwv;

    const int h  = blockIdx.y;
    const int d0 = blockIdx.x * 64;
    const int tid = threadIdx.x;
    __shared__ float t[64][65];

#pragma unroll
    for (int i = 0; i < 4; i++) {
        int idx = tid + i * 256;
        int r = idx >> 4, c4 = idx & 15;
        float4 v = *(const float4*)(W + ((size_t)h * 1024 + d0 + r) * 64 + c4 * 4);
        t[r][c4 * 4 + 0] = v.x; t[r][c4 * 4 + 1] = v.y;
        t[r][c4 * 4 + 2] = v.z; t[r][c4 * 4 + 3] = v.w;
    }
    __syncthreads();
#pragma unroll
    for (int i = 0; i < 4; i++) {
        int idx = tid + i * 256;
        int kk = idx >> 4, c4 = idx & 15;
        __half2* d = (__half2*)(OUT + ((size_t)h * 64 + kk) * 1024 + d0 + c4 * 4);
        d[0] = __floats2half2_rn(t[c4 * 4 + 0][kk], t[c4 * 4 + 1][kk]);
        d[1] = __floats2half2_rn(t[c4 * 4 + 2][kk], t[c4 * 4 + 3][kk]);
    }
}

// ---------------------------------------------------------------------------
// Shared GEMM body (unchanged from the 309us version).
// ---------------------------------------------------------------------------
__device__ __forceinline__ void hgemm_body(
    const __half* __restrict__ A, const __half* __restrict__ Bm,
    void* __restrict__ Cout, const float* __restrict__ bias, int out_half,
    char* smc, int m0, int n0)
{
    __half* As = (__half*)smc;            // [3][128][G_LD]
    __half* Bs = As + 3 * G_BUF;

    const int tid = threadIdx.x;
    const int w = tid >> 5, lane = tid & 31;
    const int wm = w & 1, wn = w >> 1;

    auto prefetch = [&](int s, int buf) {
        const int k0 = s * 64;
        __half* Ab = As + buf * G_BUF;
        __half* Bb = Bs + buf * G_BUF;
#pragma unroll
        for (int i = 0; i < 4; i++) {
            int idx = tid + i * 256;
            int r = idx >> 3, c = idx & 7;
            cp16h(&Ab[r * G_LD + c * 8], A + (size_t)(m0 + r) * 1024 + k0 + c * 8);
            cp16h(&Bb[r * G_LD + c * 8], Bm + (size_t)(n0 + r) * 1024 + k0 + c * 8);
        }
        cp_commit();
    };

    HFragC acc[4][2];
#pragma unroll
    for (int i = 0; i < 4; i++) { wmma::fill_fragment(acc[i][0], 0.0f); wmma::fill_fragment(acc[i][1], 0.0f); }

    prefetch(0, 0);
    prefetch(1, 1);
    for (int s = 0; s < 16; s++) {
        const int buf = s % 3;
        if (s < 15) cp_wait<1>(); else cp_wait<0>();
        __syncthreads();
        if (s + 2 < 16) prefetch(s + 2, (s + 2) % 3);
        __half* Ab = As + buf * G_BUF;
        __half* Bb = Bs + buf * G_BUF;
#pragma unroll
        for (int ks = 0; ks < 4; ks++) {
            HFragA a[4]; HFragBc bb[2];
#pragma unroll
            for (int i = 0; i < 4; i++)
                wmma::load_matrix_sync(a[i], &Ab[(wm * 64 + i * 16) * G_LD + ks * 16], G_LD);
#pragma unroll
            for (int j = 0; j < 2; j++)
                wmma::load_matrix_sync(bb[j], &Bb[(wn * 32 + j * 16) * G_LD + ks * 16], G_LD);
#pragma unroll
            for (int i = 0; i < 4; i++)
#pragma unroll
                for (int j = 0; j < 2; j++) wmma::mma_sync(acc[i][j], a[i], bb[j], acc[i][j]);
        }
    }
    __syncthreads();

    float* stg = (float*)smc + w * 576;
    const int r = lane >> 1, cq = (lane & 1) * 16;
    float4 bv[4];
    if (!out_half) {
#pragma unroll
        for (int q = 0; q < 4; q++)
            bv[q] = bias ? *(const float4*)&bias[n0 + wn * 32 + cq + q * 4]
                         : make_float4(0.f, 0.f, 0.f, 0.f);
    }
#pragma unroll
    for (int i = 0; i < 4; i++) {
        wmma::store_matrix_sync(stg,      acc[i][0], 36, wmma::mem_row_major);
        wmma::store_matrix_sync(stg + 16, acc[i][1], 36, wmma::mem_row_major);
        __syncwarp();
        float4 v[4];
#pragma unroll
        for (int q = 0; q < 4; q++) v[q] = *(float4*)&stg[r * 36 + cq + q * 4];
        size_t gr = (size_t)(m0 + wm * 64 + i * 16 + r) * 1024 + n0 + wn * 32 + cq;
        if (out_half) {
            __half hb[16];
#pragma unroll
            for (int q = 0; q < 4; q++) {
                ((__half2*)hb)[2 * q + 0] = __floats2half2_rn(v[q].x, v[q].y);
                ((__half2*)hb)[2 * q + 1] = __floats2half2_rn(v[q].z, v[q].w);
            }
            __half* hC = (__half*)Cout;
            *(uint4*)&hC[gr]     = ((uint4*)hb)[0];
            *(uint4*)&hC[gr + 8] = ((uint4*)hb)[1];
        } else {
            float* fC = (float*)Cout;
#pragma unroll
            for (int q = 0; q < 4; q++) {
                v[q].x += bv[q].x; v[q].y += bv[q].y; v[q].z += bv[q].z; v[q].w += bv[q].w;
                *(float4*)&fC[gr + q * 4] = v[q];
            }
        }
        __syncwarp();
    }
}

__global__ void __launch_bounds__(256, 2)
qkvproj_kernel()
{
    extern __shared__ char smc[];
    const int which = blockIdx.z;
    const __half* A = (which == 0) ? g_hxq : (which == 1) ? g_hxk : g_hxv;
    const __half* Bm = (which == 0) ? g_hwq : (which == 1) ? g_hwk : g_hwv;
    __half* C = (which == 0) ? g_q : (which == 1) ? g_k : g_v;
    hgemm_body(A, Bm, C, nullptr, 1, smc, blockIdx.x * 128, blockIdx.y * 128);
}

__global__ void __launch_bounds__(256, 2)
outproj_kernel(const float* __restrict__ bias, float* __restrict__ out)
{
    extern __shared__ char smc[];
    hgemm_body(g_ctx, g_hwp, out, bias, 0, smc, blockIdx.x * 128, blockIdx.y * 128);
}

// ---------------------------------------------------------------------------
// Kernel 2: fused attention with ONLINE softmax statistics.
// Phase 1 writes e = exp(s - m_chunk) to the strip + records chunk maxima.
// A tiny pass builds corr[chunk][row] = exp(m_c - m_fin)/s_fin.
// Phase 3 multiplies by corr (no exp), writes final fp32 probs once, and
// feeds half P into the PV MMA. The old standalone softmax pass is gone.
// ---------------------------------------------------------------------------
__global__ void __launch_bounds__(256, 2)
attn_kernel(float* __restrict__ attn)
{
    extern __shared__ char smc[];
    __half* Qs   = (__half*)smc;                    // [64][Q_LD]
    float* stats  = (float*)(smc + STAT_OFF);       // [64][2] {m_fin, s_fin}
    float* stats2 = (float*)(smc + STAT2_OFF);      // [8][64] chunk maxima -> corr
    __half* Kv   = (__half*)(smc + KV_OFF);         // [3][128][K_LD]
    float* Sc    = (float*)(smc + SC_OFF);          // [64][SC_LD] score staging
    __half* As3  = (__half*)(smc + AS3_OFF);        // [64][P_LD]
    __half* Vs3  = (__half*)(smc + VS3_OFF);        // [128][K_LD]
    float* red   = (float*)(smc + RED_OFF);         // [64][R_LD]
    float* red2  = (float*)(smc + RED2_OFF);        // [64][R_LD]

    const int bh = blockIdx.y;
    const int b = bh / H, h = bh % H;
    const int q0 = blockIdx.x * QT;
    const int tid = threadIdx.x;
    const int warp = tid >> 5, lane = tid & 31;

    float* strip = attn + ((size_t)(h * B + b) * S + q0) * S;    // [64][1024] f32

    float m_run[8], s_run[8];

    // ---- phase 1: scores chunk -> smem staging -> strip (as e-values) ----
    {
#pragma unroll
        for (int i = 0; i < 2; i++) {
            int idx = tid + i * 256;
            int r = idx >> 3, c = idx & 7;
            cp16h(&Qs[r * Q_LD + c * 8], g_q + ((size_t)(b * S + q0 + r)) * 1024 + h * 64 + c * 8);
        }
        auto prefetchK = [&](int c, int buf) {
            __half* Kb = Kv + buf * CK * K_LD;
#pragma unroll
            for (int i = 0; i < 4; i++) {
                int idx = tid + i * 256;
                int r = idx >> 3, cc = idx & 7;
                cp16h(&Kb[r * K_LD + cc * 8],
                      g_k + ((size_t)(b * S + c * CK + r)) * 1024 + h * 64 + cc * 8);
            }
            cp_commit();
        };
        prefetchK(0, 0);
        prefetchK(1, 1);

        const int qh = warp >> 2;
        const int kw = warp & 3;

        for (int c = 0; c < S / CK; c++) {
            const int buf = c % 3;
            if (c < 7) cp_wait<1>(); else cp_wait<0>();
            __syncthreads();
            if (c + 2 < 8) prefetchK(c + 2, (c + 2) % 3);
            __half* Kb = Kv + buf * CK * K_LD;

            HFragC acc[2][2];
#pragma unroll
            for (int i = 0; i < 2; i++) { wmma::fill_fragment(acc[i][0], 0.0f); wmma::fill_fragment(acc[i][1], 0.0f); }
#pragma unroll
            for (int ks = 0; ks < 4; ks++) {
                HFragA a[2]; HFragBc bb[2];
#pragma unroll
                for (int i = 0; i < 2; i++)
                    wmma::load_matrix_sync(a[i], &Qs[(qh * 32 + i * 16) * Q_LD + ks * 16], Q_LD);
#pragma unroll
                for (int j = 0; j < 2; j++)
                    wmma::load_matrix_sync(bb[j], &Kb[(kw * 32 + j * 16) * K_LD + ks * 16], K_LD);
#pragma unroll
                for (int i = 0; i < 2; i++)
#pragma unroll
                    for (int j = 0; j < 2; j++) wmma::mma_sync(acc[i][j], a[i], bb[j], acc[i][j]);
            }
#pragma unroll
            for (int i = 0; i < 2; i++)
#pragma unroll
                for (int j = 0; j < 2; j++) {
#pragma unroll
                    for (int e = 0; e < acc[i][j].num_elements; e++) acc[i][j].x[e] *= INV_SCALE;
                    wmma::store_matrix_sync(&Sc[(qh * 32 + i * 16) * SC_LD + kw * 32 + j * 16],
                                            acc[i][j], SC_LD, wmma::mem_row_major);
                }
            __syncthreads();

            // stats + copy: warp owns rows warp*8 .. warp*8+7
#pragma unroll
            for (int rr = 0; rr < 8; rr++) {
                const int row = warp * 8 + rr;
                float4 v = *(float4*)&Sc[row * SC_LD + lane * 4];
                float mc = fmaxf(fmaxf(v.x, v.y), fmaxf(v.z, v.w));
#pragma unroll
                for (int o = 16; o; o >>= 1) mc = fmaxf(mc, __shfl_xor_sync(0xffffffffu, mc, o));
                float4 e;
                e.x = __expf(v.x - mc); e.y = __expf(v.y - mc);
                e.z = __expf(v.z - mc); e.w = __expf(v.w - mc);
                float sc_ = (e.x + e.y) + (e.z + e.w);
#pragma unroll
                for (int o = 16; o; o >>= 1) sc_ += __shfl_xor_sync(0xffffffffu, sc_, o);
                if (c == 0) { m_run[rr] = mc; s_run[rr] = sc_; }
                else {
                    float mn = fmaxf(m_run[rr], mc);
                    s_run[rr] = s_run[rr] * __expf(m_run[rr] - mn) + sc_ * __expf(mc - mn);
                    m_run[rr] = mn;
                }
                if (lane == 0) stats2[c * 64 + row] = mc;
                *(float4*)&strip[(size_t)row * S + c * CK + lane * 4] = e;
            }
        }
    }

    // finalize stats, build corr table
    if (lane == 0) {
#pragma unroll
        for (int rr = 0; rr < 8; rr++) {
            stats[(warp * 8 + rr) * 2 + 0] = m_run[rr];
            stats[(warp * 8 + rr) * 2 + 1] = s_run[rr];
        }
    }
    __syncthreads();
#pragma unroll
    for (int t = tid; t < 512; t += 256) {
        int r = t & 63;
        stats2[t] = __expf(stats2[t] - stats[r * 2]) / stats[r * 2 + 1];
    }
    __syncthreads();

    // ---- phase 3: p = e * corr; write final probs; ctx = P V ----
    {
        const int kg = warp >> 2;
        const int qh = (warp >> 1) & 1;
        const int vn = warp & 1;

        HFragC pacc[2][2];
#pragma unroll
        for (int i = 0; i < 2; i++) { wmma::fill_fragment(pacc[i][0], 0.0f); wmma::fill_fragment(pacc[i][1], 0.0f); }

        for (int c = 0; c < S / CK; c++) {
#pragma unroll
            for (int i = 0; i < 4; i++) {
                int idx = tid + i * 256;
                int r = idx >> 3, cc = idx & 7;
                cp16h(&Vs3[r * K_LD + cc * 8],
                      g_v + ((size_t)(b * S + c * CK + r)) * 1024 + h * 64 + cc * 8);
            }
            cp_commit();
#pragma unroll
            for (int i = 0; i < 8; i++) {
                const int r = warp + 8 * i;      // lin = tid + i*256 decomposition
                const float cr = stats2[c * 64 + r];
                float4 v = *(const float4*)&strip[(size_t)r * S + c * CK + lane * 4];
                v.x *= cr; v.y *= cr; v.z *= cr; v.w *= cr;
                *(float4*)&strip[(size_t)r * S + c * CK + lane * 4] = v;   // final probs
                uint2 pk;
                ((__half2*)&pk)[0] = __floats2half2_rn(v.x, v.y);
                ((__half2*)&pk)[1] = __floats2half2_rn(v.z, v.w);
                *(uint2*)&As3[r * P_LD + lane * 4] = pk;
            }
            cp_wait<0>();
            __syncthreads();
#pragma unroll
            for (int ks = 0; ks < 4; ks++) {
                const int kk = kg * 64 + ks * 16;
                HFragA a[2]; HFragBr bb[2];
#pragma unroll
                for (int i = 0; i < 2; i++)
                    wmma::load_matrix_sync(a[i], &As3[(qh * 32 + i * 16) * P_LD + kk], P_LD);
#pragma unroll
                for (int j = 0; j < 2; j++)
                    wmma::load_matrix_sync(bb[j], &Vs3[kk * K_LD + vn * 32 + j * 16], K_LD);
#pragma unroll
                for (int i = 0; i < 2; i++)
#pragma unroll
                    for (int j = 0; j < 2; j++) wmma::mma_sync(pacc[i][j], a[i], bb[j], pacc[i][j]);
            }
            __syncthreads();
        }

        if (kg == 1) {
#pragma unroll
            for (int i = 0; i < 2; i++)
#pragma unroll
                for (int j = 0; j < 2; j++)
                    wmma::store_matrix_sync(&red[(qh * 32 + i * 16) * R_LD + vn * 32 + j * 16],
                                            pacc[i][j], R_LD, wmma::mem_row_major);
        }
        __syncthreads();
        if (kg == 0) {
#pragma unroll
            for (int i = 0; i < 2; i++)
#pragma unroll
                for (int j = 0; j < 2; j++) {
                    HFragC other;
                    wmma::load_matrix_sync(other, &red[(qh * 32 + i * 16) * R_LD + vn * 32 + j * 16],
                                           R_LD, wmma::mem_row_major);
#pragma unroll
                    for (int e = 0; e < pacc[i][j].num_elements; e++) pacc[i][j].x[e] += other.x[e];
                    wmma::store_matrix_sync(&red2[(qh * 32 + i * 16) * R_LD + vn * 32 + j * 16],
                                            pacc[i][j], R_LD, wmma::mem_row_major);
                }
        }
        __syncthreads();
#pragma unroll
        for (int i = 0; i < 8; i++) {
            int lin = tid + i * 256;
            int r = lin >> 5, c2 = lin & 31;
            float2 t = *(float2*)&red2[r * R_LD + c2 * 2];
            __half2* dst = (__half2*)(g_ctx + ((size_t)(b * S + q0 + r)) * 1024 + h * 64 + c2 * 2);
            *dst = __floats2half2_rn(t.x, t.y);
        }
    }
}

// ---------------------------------------------------------------------------

extern "C" void kernel_launch(void* const* d_in, const int* in_sizes, int n_in,
                              void* d_out, int out_size)
{
    const float* query  = (const float*)d_in[0];
    const float* key    = (const float*)d_in[1];
    const float* value  = (const float*)d_in[2];
    const float* w_q    = (const float*)d_in[3];
    const float* w_k    = (const float*)d_in[4];
    const float* w_v    = (const float*)d_in[5];
    const float* w_proj = (const float*)d_in[6];
    const float* b_proj = (const float*)d_in[7];

    float* out  = (float*)d_out;            // [B, S, D]
    float* attn = out + OUT_ELEMS;          // [H*B, S, S]

    cudaFuncSetAttribute(qkvproj_kernel, cudaFuncAttributeMaxDynamicSharedMemorySize, (int)GEMM_SMEM);
    cudaFuncSetAttribute(outproj_kernel, cudaFuncAttributeMaxDynamicSharedMemorySize, (int)GEMM_SMEM);
    cudaFuncSetAttribute(attn_kernel, cudaFuncAttributeMaxDynamicSharedMemorySize, (int)ATTN_SMEM);

    __half* hwp;
    cudaGetSymbolAddress((void**)&hwp, g_hwp);

    const int nX4 = (int)((size_t)B * S * D / 4);   // 1,048,576
    const int nP4 = (int)((size_t)D * D / 4);       // 262,144
    f2h3_kernel<<<dim3((nX4 + 255) / 256, 3), 256>>>(
        (const float4*)query, (const float4*)key, (const float4*)value, nX4);
    f2h_kernel<<<(nP4 + 255) / 256, 256>>>((const float4*)w_proj, (__half2*)hwp, nP4);
    wtrans_kernel<<<dim3(16, 16, 3), 256>>>(w_q, w_k, w_v);

    qkvproj_kernel<<<dim3(32, 8, 3), 256, GEMM_SMEM>>>();
    attn_kernel<<<dim3(S / QT, HB), 256, ATTN_SMEM>>>(attn);
    outproj_kernel<<<dim3(32, 8), 256, GEMM_SMEM>>>(b_proj, out);
}

// round 16
// speedup vs baseline: 1.1771x; 1.1771x over previous
#include <cuda_runtime.h>
#include <cstdint>
#include <cuda_fp16.h>
#include <mma.h>

using namespace nvcuda;

namespace {
constexpr int B  = 4;
constexpr int H  = 16;
constexpr int S  = 1024;
constexpr int D  = 1024;
constexpr int HB = H * B;
constexpr float INV_SCALE = 1.0f / 32.0f;        // 1/sqrt(D)
constexpr size_t OUT_ELEMS = (size_t)B * S * D;

// half GEMM tiling (3-stage pipeline)
constexpr int G_LD = 72;
constexpr int G_BUF = 128 * G_LD;
constexpr size_t GEMM_SMEM = (size_t)6 * G_BUF * 2;   // 110592

// attention tiling
constexpr int QT = 64;
constexpr int CK = 128;
constexpr int Q_LD = 72;     // halfs
constexpr int K_LD = 72;     // halfs
constexpr int P_LD = 136;    // halfs
constexpr int R_LD = 68;     // floats
constexpr int KV_OFF = QT * Q_LD * 2;            // 9216 bytes
constexpr int KBUF_BYTES = CK * K_LD * 2;        // 18432
constexpr int PATCH_OFF = KV_OFF + 3 * KBUF_BYTES;   // 64512
constexpr int PATCH_WARP = 32 * 36;                  // floats per warp patch
constexpr size_t ATTN_SMEM = (size_t)PATCH_OFF + 8 * PATCH_WARP * 4;   // 101376
}

// Scratch (__device__ globals; allocation-free rule)
__device__ __half g_hxq[(size_t)B * S * D];
__device__ __half g_hxk[(size_t)B * S * D];
__device__ __half g_hxv[(size_t)B * S * D];
__device__ __half g_hwq[(size_t)D * D];          // transposed [n][d]
__device__ __half g_hwk[(size_t)D * D];
__device__ __half g_hwv[(size_t)D * D];
__device__ __half g_hwp[(size_t)D * D];          // [n][k]
__device__ __half g_q[(size_t)B * S * D];        // proj outputs, [m][h*64+k]
__device__ __half g_k[(size_t)B * S * D];
__device__ __half g_v[(size_t)B * S * D];
__device__ __half g_ctx[(size_t)B * S * D];      // [m][h*64+v]

using HFragA  = wmma::fragment<wmma::matrix_a, 16, 16, 16, __half, wmma::row_major>;
using HFragBr = wmma::fragment<wmma::matrix_b, 16, 16, 16, __half, wmma::row_major>;
using HFragBc = wmma::fragment<wmma::matrix_b, 16, 16, 16, __half, wmma::col_major>;
using HFragC  = wmma::fragment<wmma::accumulator, 16, 16, 16, float>;

__device__ __forceinline__ void cp16h(__half* dst, const __half* src) {
    unsigned int s = (unsigned int)__cvta_generic_to_shared(dst);
    asm volatile("cp.async.cg.shared.global [%0], [%1], 16;" :: "r"(s), "l"(src));
}
__device__ __forceinline__ void cp_commit() { asm volatile("cp.async.commit_group;"); }
template <int N> __device__ __forceinline__ void cp_wait() {
    asm volatile("cp.async.wait_group %0;" :: "n"(N));
}

// ---------------------------------------------------------------------------
// Kernel 0a: fp32 -> fp16 for the three X tensors (y-indexed).
// ---------------------------------------------------------------------------
__global__ void __launch_bounds__(256)
f2h3_kernel(const float4* __restrict__ s0, const float4* __restrict__ s1,
            const float4* __restrict__ s2, int n4)
{
    const float4* src = (blockIdx.y == 0) ? s0 : (blockIdx.y == 1) ? s1 : s2;
    __half2* dst = (blockIdx.y == 0) ? (__half2*)g_hxq
                 : (blockIdx.y == 1) ? (__half2*)g_hxk : (__half2*)g_hxv;
    int i = blockIdx.x * 256 + threadIdx.x;
    if (i < n4) {
        float4 v = src[i];
        dst[2 * i + 0] = __floats2half2_rn(v.x, v.y);
        dst[2 * i + 1] = __floats2half2_rn(v.z, v.w);
    }
}

__global__ void __launch_bounds__(256)
f2h_kernel(const float4* __restrict__ src, __half2* __restrict__ dst, int n4)
{
    int i = blockIdx.x * 256 + threadIdx.x;
    if (i < n4) {
        float4 v = src[i];
        dst[2 * i + 0] = __floats2half2_rn(v.x, v.y);
        dst[2 * i + 1] = __floats2half2_rn(v.z, v.w);
    }
}

// ---------------------------------------------------------------------------
// Kernel 0b: W[h][d][kk] -> Wt[(h*64+kk)][d] in fp16. grid (16, 16, 3).
// ---------------------------------------------------------------------------
__global__ void __launch_bounds__(256)
wtrans_kernel(const float* __restrict__ wq, const float* __restrict__ wk,
              const float* __restrict__ wv)
{
    const int which = blockIdx.z;
    const float* W = (which == 0) ? wq : (which == 1) ? wk : wv;
    __half* OUT    = (which == 0) ? g_hwq : (which == 1) ? g_hwk : g_hwv;

    const int h  = blockIdx.y;
    const int d0 = blockIdx.x * 64;
    const int tid = threadIdx.x;
    __shared__ float t[64][65];

#pragma unroll
    for (int i = 0; i < 4; i++) {
        int idx = tid + i * 256;
        int r = idx >> 4, c4 = idx & 15;
        float4 v = *(const float4*)(W + ((size_t)h * 1024 + d0 + r) * 64 + c4 * 4);
        t[r][c4 * 4 + 0] = v.x; t[r][c4 * 4 + 1] = v.y;
        t[r][c4 * 4 + 2] = v.z; t[r][c4 * 4 + 3] = v.w;
    }
    __syncthreads();
#pragma unroll
    for (int i = 0; i < 4; i++) {
        int idx = tid + i * 256;
        int kk = idx >> 4, c4 = idx & 15;
        __half2* d = (__half2*)(OUT + ((size_t)h * 64 + kk) * 1024 + d0 + c4 * 4);
        d[0] = __floats2half2_rn(t[c4 * 4 + 0][kk], t[c4 * 4 + 1][kk]);
        d[1] = __floats2half2_rn(t[c4 * 4 + 2][kk], t[c4 * 4 + 3][kk]);
    }
}

// ---------------------------------------------------------------------------
// Shared GEMM body (unchanged from the 309us version).
// ---------------------------------------------------------------------------
__device__ __forceinline__ void hgemm_body(
    const __half* __restrict__ A, const __half* __restrict__ Bm,
    void* __restrict__ Cout, const float* __restrict__ bias, int out_half,
    char* smc, int m0, int n0)
{
    __half* As = (__half*)smc;            // [3][128][G_LD]
    __half* Bs = As + 3 * G_BUF;

    const int tid = threadIdx.x;
    const int w = tid >> 5, lane = tid & 31;
    const int wm = w & 1, wn = w >> 1;

    auto prefetch = [&](int s, int buf) {
        const int k0 = s * 64;
        __half* Ab = As + buf * G_BUF;
        __half* Bb = Bs + buf * G_BUF;
#pragma unroll
        for (int i = 0; i < 4; i++) {
            int idx = tid + i * 256;
            int r = idx >> 3, c = idx & 7;
            cp16h(&Ab[r * G_LD + c * 8], A + (size_t)(m0 + r) * 1024 + k0 + c * 8);
            cp16h(&Bb[r * G_LD + c * 8], Bm + (size_t)(n0 + r) * 1024 + k0 + c * 8);
        }
        cp_commit();
    };

    HFragC acc[4][2];
#pragma unroll
    for (int i = 0; i < 4; i++) { wmma::fill_fragment(acc[i][0], 0.0f); wmma::fill_fragment(acc[i][1], 0.0f); }

    prefetch(0, 0);
    prefetch(1, 1);
    for (int s = 0; s < 16; s++) {
        const int buf = s % 3;
        if (s < 15) cp_wait<1>(); else cp_wait<0>();
        __syncthreads();
        if (s + 2 < 16) prefetch(s + 2, (s + 2) % 3);
        __half* Ab = As + buf * G_BUF;
        __half* Bb = Bs + buf * G_BUF;
#pragma unroll
        for (int ks = 0; ks < 4; ks++) {
            HFragA a[4]; HFragBc bb[2];
#pragma unroll
            for (int i = 0; i < 4; i++)
                wmma::load_matrix_sync(a[i], &Ab[(wm * 64 + i * 16) * G_LD + ks * 16], G_LD);
#pragma unroll
            for (int j = 0; j < 2; j++)
                wmma::load_matrix_sync(bb[j], &Bb[(wn * 32 + j * 16) * G_LD + ks * 16], G_LD);
#pragma unroll
            for (int i = 0; i < 4; i++)
#pragma unroll
                for (int j = 0; j < 2; j++) wmma::mma_sync(acc[i][j], a[i], bb[j], acc[i][j]);
        }
    }
    __syncthreads();

    float* stg = (float*)smc + w * 576;
    const int r = lane >> 1, cq = (lane & 1) * 16;
    float4 bv[4];
    if (!out_half) {
#pragma unroll
        for (int q = 0; q < 4; q++)
            bv[q] = bias ? *(const float4*)&bias[n0 + wn * 32 + cq + q * 4]
                         : make_float4(0.f, 0.f, 0.f, 0.f);
    }
#pragma unroll
    for (int i = 0; i < 4; i++) {
        wmma::store_matrix_sync(stg,      acc[i][0], 36, wmma::mem_row_major);
        wmma::store_matrix_sync(stg + 16, acc[i][1], 36, wmma::mem_row_major);
        __syncwarp();
        float4 v[4];
#pragma unroll
        for (int q = 0; q < 4; q++) v[q] = *(float4*)&stg[r * 36 + cq + q * 4];
        size_t gr = (size_t)(m0 + wm * 64 + i * 16 + r) * 1024 + n0 + wn * 32 + cq;
        if (out_half) {
            __half hb[16];
#pragma unroll
            for (int q = 0; q < 4; q++) {
                ((__half2*)hb)[2 * q + 0] = __floats2half2_rn(v[q].x, v[q].y);
                ((__half2*)hb)[2 * q + 1] = __floats2half2_rn(v[q].z, v[q].w);
            }
            __half* hC = (__half*)Cout;
            *(uint4*)&hC[gr]     = ((uint4*)hb)[0];
            *(uint4*)&hC[gr + 8] = ((uint4*)hb)[1];
        } else {
            float* fC = (float*)Cout;
#pragma unroll
            for (int q = 0; q < 4; q++) {
                v[q].x += bv[q].x; v[q].y += bv[q].y; v[q].z += bv[q].z; v[q].w += bv[q].w;
                *(float4*)&fC[gr + q * 4] = v[q];
            }
        }
        __syncwarp();
    }
}

__global__ void __launch_bounds__(256, 2)
qkvproj_kernel()
{
    extern __shared__ char smc[];
    const int which = blockIdx.z;
    const __half* A = (which == 0) ? g_hxq : (which == 1) ? g_hxk : g_hxv;
    const __half* Bm = (which == 0) ? g_hwq : (which == 1) ? g_hwk : g_hwv;
    __half* C = (which == 0) ? g_q : (which == 1) ? g_k : g_v;
    hgemm_body(A, Bm, C, nullptr, 1, smc, blockIdx.x * 128, blockIdx.y * 128);
}

__global__ void __launch_bounds__(256, 2)
outproj_kernel(const float* __restrict__ bias, float* __restrict__ out)
{
    extern __shared__ char smc[];
    hgemm_body(g_ctx, g_hwp, out, bias, 0, smc, blockIdx.x * 128, blockIdx.y * 128);
}

// ---------------------------------------------------------------------------
// Kernel 2: fused attention (R14 design). P1 strip stores now staged through
// warp-private smem patches -> 128B-coalesced gmem writes (syncwarp only).
// ---------------------------------------------------------------------------
__global__ void __launch_bounds__(256, 2)
attn_kernel(float* __restrict__ attn)
{
    extern __shared__ char smc[];
    __half* Qs = (__half*)smc;                     // [64][Q_LD]
    __half* Kv = (__half*)(smc + KV_OFF);          // [3][128][K_LD]
    __half* As3 = (__half*)(smc + KV_OFF);         // [64][P_LD]   (phase 3 alias)
    __half* Vs3 = (__half*)(smc + KV_OFF + QT * P_LD * 2);   // [128][K_LD]
    float* red  = (float*)(smc + KV_OFF);                    // [64][R_LD]
    float* red2 = (float*)(smc + KV_OFF + QT * P_LD * 2);    // [64][R_LD]

    const int bh = blockIdx.y;
    const int b = bh / H, h = bh % H;
    const int q0 = blockIdx.x * QT;
    const int tid = threadIdx.x;
    const int warp = tid >> 5, lane = tid & 31;

    float* strip = attn + ((size_t)(h * B + b) * S + q0) * S;    // [64][1024] f32

    // ---- phase 1: scores = QK^T/32 -> strip (coalesced via warp patch) ----
    {
#pragma unroll
        for (int i = 0; i < 2; i++) {
            int idx = tid + i * 256;
            int r = idx >> 3, c = idx & 7;
            cp16h(&Qs[r * Q_LD + c * 8], g_q + ((size_t)(b * S + q0 + r)) * 1024 + h * 64 + c * 8);
        }
        auto prefetchK = [&](int c, int buf) {
            __half* Kb = Kv + buf * CK * K_LD;
#pragma unroll
            for (int i = 0; i < 4; i++) {
                int idx = tid + i * 256;
                int r = idx >> 3, cc = idx & 7;
                cp16h(&Kb[r * K_LD + cc * 8],
                      g_k + ((size_t)(b * S + c * CK + r)) * 1024 + h * 64 + cc * 8);
            }
            cp_commit();
        };
        prefetchK(0, 0);
        prefetchK(1, 1);

        const int qh = warp >> 2;
        const int kw = warp & 3;
        float* patch = (float*)(smc + PATCH_OFF) + warp * PATCH_WARP;   // [32][36]

        for (int c = 0; c < S / CK; c++) {
            const int buf = c % 3;
            if (c < 7) cp_wait<1>(); else cp_wait<0>();
            __syncthreads();
            if (c + 2 < 8) prefetchK(c + 2, (c + 2) % 3);
            __half* Kb = Kv + buf * CK * K_LD;

            HFragC acc[2][2];
#pragma unroll
            for (int i = 0; i < 2; i++) { wmma::fill_fragment(acc[i][0], 0.0f); wmma::fill_fragment(acc[i][1], 0.0f); }
#pragma unroll
            for (int ks = 0; ks < 4; ks++) {
                HFragA a[2]; HFragBc bb[2];
#pragma unroll
                for (int i = 0; i < 2; i++)
                    wmma::load_matrix_sync(a[i], &Qs[(qh * 32 + i * 16) * Q_LD + ks * 16], Q_LD);
#pragma unroll
                for (int j = 0; j < 2; j++)
                    wmma::load_matrix_sync(bb[j], &Kb[(kw * 32 + j * 16) * K_LD + ks * 16], K_LD);
#pragma unroll
                for (int i = 0; i < 2; i++)
#pragma unroll
                    for (int j = 0; j < 2; j++) wmma::mma_sync(acc[i][j], a[i], bb[j], acc[i][j]);
            }
            // stage 32x32 tile in warp-private patch, then coalesced strip write
#pragma unroll
            for (int i = 0; i < 2; i++)
#pragma unroll
                for (int j = 0; j < 2; j++) {
#pragma unroll
                    for (int e = 0; e < acc[i][j].num_elements; e++) acc[i][j].x[e] *= INV_SCALE;
                    wmma::store_matrix_sync(&patch[(i * 16) * 36 + j * 16], acc[i][j], 36,
                                            wmma::mem_row_major);
                }
            __syncwarp();
#pragma unroll
            for (int it = 0; it < 4; it++) {
                const int row = it * 8 + (lane >> 2);
                const int c8 = (lane & 3) * 8;
                float4 v0 = *(float4*)&patch[row * 36 + c8];
                float4 v1 = *(float4*)&patch[row * 36 + c8 + 4];
                float* dst = strip + (size_t)(qh * 32 + row) * S + c * CK + kw * 32;
                *(float4*)&dst[c8]     = v0;
                *(float4*)&dst[c8 + 4] = v1;
            }
            __syncwarp();
        }
        __syncthreads();
    }

    // ---- phase 2: softmax in place (f32) ----
#pragma unroll
    for (int rr = 0; rr < 8; rr++) {
        const int row = warp * 8 + rr;
        float* p = strip + (size_t)row * S;
        float4 v[8];
#pragma unroll
        for (int i = 0; i < 8; i++) v[i] = *(float4*)&p[i * 128 + lane * 4];
        float m = -1e30f;
#pragma unroll
        for (int i = 0; i < 8; i++)
            m = fmaxf(m, fmaxf(fmaxf(v[i].x, v[i].y), fmaxf(v[i].z, v[i].w)));
#pragma unroll
        for (int o = 16; o; o >>= 1) m = fmaxf(m, __shfl_xor_sync(0xffffffffu, m, o));
        float s = 0.0f;
#pragma unroll
        for (int i = 0; i < 8; i++) {
            v[i].x = __expf(v[i].x - m); v[i].y = __expf(v[i].y - m);
            v[i].z = __expf(v[i].z - m); v[i].w = __expf(v[i].w - m);
            s += (v[i].x + v[i].y) + (v[i].z + v[i].w);
        }
#pragma unroll
        for (int o = 16; o; o >>= 1) s += __shfl_xor_sync(0xffffffffu, s, o);
        const float inv = 1.0f / s;
#pragma unroll
        for (int i = 0; i < 8; i++) {
            float4 q; q.x = v[i].x * inv; q.y = v[i].y * inv; q.z = v[i].z * inv; q.w = v[i].w * inv;
            *(float4*)&p[i * 128 + lane * 4] = q;
        }
    }
    __syncthreads();

    // ---- phase 3: ctx = P V (P read back fp32 from strip, converted here) ----
    {
        const int kg = warp >> 2;
        const int qh = (warp >> 1) & 1;
        const int vn = warp & 1;

        HFragC pacc[2][2];
#pragma unroll
        for (int i = 0; i < 2; i++) { wmma::fill_fragment(pacc[i][0], 0.0f); wmma::fill_fragment(pacc[i][1], 0.0f); }

        for (int c = 0; c < S / CK; c++) {
#pragma unroll
            for (int i = 0; i < 4; i++) {
                int idx = tid + i * 256;
                int r = idx >> 3, cc = idx & 7;
                cp16h(&Vs3[r * K_LD + cc * 8],
                      g_v + ((size_t)(b * S + c * CK + r)) * 1024 + h * 64 + cc * 8);
            }
            cp_commit();
#pragma unroll
            for (int i = 0; i < 8; i++) {
                int lin = tid + i * 256;
                int r = lin >> 5, c4 = lin & 31;
                float4 v = *(const float4*)&strip[(size_t)r * S + c * CK + c4 * 4];
                uint2 pk;
                ((__half2*)&pk)[0] = __floats2half2_rn(v.x, v.y);
                ((__half2*)&pk)[1] = __floats2half2_rn(v.z, v.w);
                *(uint2*)&As3[r * P_LD + c4 * 4] = pk;
            }
            cp_wait<0>();
            __syncthreads();
#pragma unroll
            for (int ks = 0; ks < 4; ks++) {
                const int kk = kg * 64 + ks * 16;
                HFragA a[2]; HFragBr bb[2];
#pragma unroll
                for (int i = 0; i < 2; i++)
                    wmma::load_matrix_sync(a[i], &As3[(qh * 32 + i * 16) * P_LD + kk], P_LD);
#pragma unroll
                for (int j = 0; j < 2; j++)
                    wmma::load_matrix_sync(bb[j], &Vs3[kk * K_LD + vn * 32 + j * 16], K_LD);
#pragma unroll
                for (int i = 0; i < 2; i++)
#pragma unroll
                    for (int j = 0; j < 2; j++) wmma::mma_sync(pacc[i][j], a[i], bb[j], pacc[i][j]);
            }
            __syncthreads();
        }

        if (kg == 1) {
#pragma unroll
            for (int i = 0; i < 2; i++)
#pragma unroll
                for (int j = 0; j < 2; j++)
                    wmma::store_matrix_sync(&red[(qh * 32 + i * 16) * R_LD + vn * 32 + j * 16],
                                            pacc[i][j], R_LD, wmma::mem_row_major);
        }
        __syncthreads();
        if (kg == 0) {
#pragma unroll
            for (int i = 0; i < 2; i++)
#pragma unroll
                for (int j = 0; j < 2; j++) {
                    HFragC other;
                    wmma::load_matrix_sync(other, &red[(qh * 32 + i * 16) * R_LD + vn * 32 + j * 16],
                                           R_LD, wmma::mem_row_major);
#pragma unroll
                    for (int e = 0; e < pacc[i][j].num_elements; e++) pacc[i][j].x[e] += other.x[e];
                    wmma::store_matrix_sync(&red2[(qh * 32 + i * 16) * R_LD + vn * 32 + j * 16],
                                            pacc[i][j], R_LD, wmma::mem_row_major);
                }
        }
        __syncthreads();
#pragma unroll
        for (int i = 0; i < 8; i++) {
            int lin = tid + i * 256;
            int r = lin >> 5, c2 = lin & 31;
            float2 t = *(float2*)&red2[r * R_LD + c2 * 2];
            __half2* dst = (__half2*)(g_ctx + ((size_t)(b * S + q0 + r)) * 1024 + h * 64 + c2 * 2);
            *dst = __floats2half2_rn(t.x, t.y);
        }
    }
}

// ---------------------------------------------------------------------------

extern "C" void kernel_launch(void* const* d_in, const int* in_sizes, int n_in,
                              void* d_out, int out_size)
{
    const float* query  = (const float*)d_in[0];
    const float* key    = (const float*)d_in[1];
    const float* value  = (const float*)d_in[2];
    const float* w_q    = (const float*)d_in[3];
    const float* w_k    = (const float*)d_in[4];
    const float* w_v    = (const float*)d_in[5];
    const float* w_proj = (const float*)d_in[6];
    const float* b_proj = (const float*)d_in[7];

    float* out  = (float*)d_out;            // [B, S, D]
    float* attn = out + OUT_ELEMS;          // [H*B, S, S]

    cudaFuncSetAttribute(qkvproj_kernel, cudaFuncAttributeMaxDynamicSharedMemorySize, (int)GEMM_SMEM);
    cudaFuncSetAttribute(outproj_kernel, cudaFuncAttributeMaxDynamicSharedMemorySize, (int)GEMM_SMEM);
    cudaFuncSetAttribute(attn_kernel, cudaFuncAttributeMaxDynamicSharedMemorySize, (int)ATTN_SMEM);

    __half* hwp;
    cudaGetSymbolAddress((void**)&hwp, g_hwp);

    const int nX4 = (int)((size_t)B * S * D / 4);   // 1,048,576
    const int nP4 = (int)((size_t)D * D / 4);       // 262,144
    f2h3_kernel<<<dim3((nX4 + 255) / 256, 3), 256>>>(
        (const float4*)query, (const float4*)key, (const float4*)value, nX4);
    f2h_kernel<<<(nP4 + 255) / 256, 256>>>((const float4*)w_proj, (__half2*)hwp, nP4);
    wtrans_kernel<<<dim3(16, 16, 3), 256>>>(w_q, w_k, w_v);

    qkvproj_kernel<<<dim3(32, 8, 3), 256, GEMM_SMEM>>>();
    attn_kernel<<<dim3(S / QT, HB), 256, ATTN_SMEM>>>(attn);
    outproj_kernel<<<dim3(32, 8), 256, GEMM_SMEM>>>(b_proj, out);
}